// round 8
// baseline (speedup 1.0000x reference)
#include <cuda_runtime.h>
#include <math_constants.h>

#define PI_F 3.14159265358979323846f
#define SPLIT 4   // CTAs per box

// Per-(box,slice) partials (supports N*SPLIT <= 16384; actual 4096)
__device__ float        g_psum[16384];
__device__ int          g_pcnt[16384];
__device__ unsigned int g_done = 0;   // last-block ticket; reset by last block each call

__device__ __forceinline__ float frcp_approx(float x) {
    float r;
    asm("rcp.approx.f32 %0, %1;" : "=f"(r) : "f"(x));
    return r;
}

struct BoxConst {
    float k1, k2;
    float bs[4];
    float midx[4], halfx[4], midy[4], halfy[4];   // float-space bounds (pre-shrunk)
};

// Process 4 points (q0,q1 hold xy pairs, d4 their densities) against the box.
__device__ __forceinline__ void process4(const BoxConst& C,
                                         float4 q0, float4 q1, float4 d4,
                                         float& lsum, int& lcnt) {
    const float PX[4] = {q0.x, q0.z, q1.x, q1.z};
    const float PY[4] = {q0.y, q0.w, q1.y, q1.w};
    const float DN[4] = {d4.x, d4.y, d4.z, d4.w};

#pragma unroll
    for (int h = 0; h < 4; h++) {
        const float px = (PX[h] == 0.0f) ? 0.0001f : PX[h];
        const float py = PY[h];
        const float slope = py * frcp_approx(px);
        const float s1 = 1.0f + fabsf(slope);     // dis = |ix-px| * s1

        const float rA = frcp_approx(slope - C.k1);   // edges 0, 2
        const float rB = frcp_approx(slope - C.k2);   // edges 1, 3

        float best_aix = CUDART_INF_F;   // argmin key: |ix| (monotone with cen)
        float best_ix  = 0.0f;
        int   m = 0;

#pragma unroll
        for (int j = 0; j < 4; j++) {
            const float r  = (j & 1) ? rB : rA;
            const float ix = C.bs[j] * r;
            const float iy = ix * slope;
            // float-space mask: equivalent to the rint(1e4*...) integer test
            // except on measure-zero half-integer ties
            const bool mask = (fabsf(ix - C.midx[j]) < C.halfx[j]) |
                              (fabsf(iy - C.midy[j]) < C.halfy[j]);
            m += mask ? 1 : 0;
            const bool better = mask & (fabsf(ix) < best_aix);
            best_aix = better ? fabsf(ix) : best_aix;
            best_ix  = better ? ix : best_ix;
        }

        if (m == 2) {
            const float dis = fabsf(best_ix - px) * s1;
            lsum = fmaf(dis, frcp_approx(DN[h]), lsum);
            lcnt += 1;
        }
    }
}

__global__ void __launch_bounds__(128, 9)
box_kernel(const float* __restrict__ wl,
           const float* __restrict__ Ry,
           const float4* __restrict__ points4,   // 2 points per float4
           const float4* __restrict__ density4,  // 4 densities per float4
           const float* __restrict__ center,
           float* __restrict__ out,
           int P) {
    const int c = blockIdx.x;
    const int n = c >> 2;        // box
    const int s = c & 3;         // slice within box
    const int t = threadIdx.x;

    // setup: [0]=k1 [1]=k2 [2..5]=bs [6..9]=midx [10..13]=halfx [14..17]=midy [18..21]=halfy
    __shared__ float s_set[22];
    __shared__ int   s_last;

    if (t == 0) {
        const float w  = wl[2 * n];
        const float l  = wl[2 * n + 1];
        const float ry = Ry[n];
        const float c0 = center[2 * n];
        const float c1 = center[2 * n + 1];

        const float init_theta = atanf(w / l);
        const float length     = sqrtf(w * w + l * l) * 0.5f;

        float angs[4];
        angs[0] = init_theta + ry;
        angs[1] = PI_F - init_theta + ry;
        angs[2] = PI_F + init_theta + ry;
        angs[3] = -init_theta + ry;

        float cx[4], cy[4];
#pragma unroll
        for (int j = 0; j < 4; j++) {
            cx[j] = length * cosf(angs[j]) + c0;
            cy[j] = length * sinf(angs[j]) + c1;
        }

        float ry2 = ry;
        if (ry2 == PI_F * 0.5f) ry2 -= 0.0001f;
        if (ry2 == 0.0f)        ry2 += 0.0001f;
        const float k1 = tanf(ry2);
        const float k2 = tanf(ry2 + PI_F * 0.5f);

        s_set[0] = k1;
        s_set[1] = k2;
        // bs order = {b11, b22, b12, b21}
        s_set[2] = cy[0] - k1 * cx[0];   // b11
        s_set[3] = cy[2] - k2 * cx[2];   // b22
        s_set[4] = cy[2] - k1 * cx[2];   // b12
        s_set[5] = cy[0] - k2 * cx[0];   // b21

        float cxr[4], cyr[4];
#pragma unroll
        for (int j = 0; j < 4; j++) {
            cxr[j] = rintf(cx[j] * 10000.0f);
            cyr[j] = rintf(cy[j] * 10000.0f);
        }
        const int nxt[4] = {1, 2, 3, 0};
#pragma unroll
        for (int j = 0; j < 4; j++) {
            const int jn = nxt[j];
            const float lox = fminf(cxr[j], cxr[jn]);
            const float hix = fmaxf(cxr[j], cxr[jn]);
            const float loy = fminf(cyr[j], cyr[jn]);
            const float hiy = fmaxf(cyr[j], cyr[jn]);
            // shrink by 0.5 (rint threshold), rescale to float space
            const float loxp = (lox + 0.5f) * 1e-4f;
            const float hixp = (hix - 0.5f) * 1e-4f;
            const float loyp = (loy + 0.5f) * 1e-4f;
            const float hiyp = (hiy - 0.5f) * 1e-4f;
            s_set[6  + j] = 0.5f * (loxp + hixp);   // midx
            s_set[10 + j] = 0.5f * (hixp - loxp);   // halfx (<=0 => always-false, matches ref)
            s_set[14 + j] = 0.5f * (loyp + hiyp);   // midy
            s_set[18 + j] = 0.5f * (hiyp - loyp);   // halfy
        }
    }
    __syncthreads();

    BoxConst C;
    C.k1 = s_set[0];
    C.k2 = s_set[1];
#pragma unroll
    for (int j = 0; j < 4; j++) {
        C.bs[j]    = s_set[2 + j];
        C.midx[j]  = s_set[6 + j];
        C.halfx[j] = s_set[10 + j];
        C.midy[j]  = s_set[14 + j];
        C.halfy[j] = s_set[18 + j];
    }

    // This CTA's slice: points [s*P/4, (s+1)*P/4)
    const float4* pts4 = points4  + (size_t)n * (P / 2) + (size_t)s * (P / 8);
    const float4* dns4 = density4 + (size_t)n * (P / 4) + (size_t)s * (P / 16);

    float lsum = 0.0f;
    int   lcnt = 0;

    const int iters = P / 16;   // 4 points per iteration over P/4 points
    for (int i = t; i < iters; i += 128) {
        const float4 a0 = pts4[2 * i];
        const float4 a1 = pts4[2 * i + 1];
        const float4 da = dns4[i];
        process4(C, a0, a1, da, lsum, lcnt);
    }

    // ---- block reduction (128 threads) ----
    __shared__ float ssum[128];
    __shared__ int   scnt[128];
    ssum[t] = lsum;
    scnt[t] = lcnt;
    __syncthreads();
#pragma unroll
    for (int off = 64; off > 0; off >>= 1) {
        if (t < off) {
            ssum[t] += ssum[t + off];
            scnt[t] += scnt[t + off];
        }
        __syncthreads();
    }

    if (t == 0) {
        g_psum[c] = ssum[0];
        g_pcnt[c] = scnt[0];
        __threadfence();
        const unsigned int ticket = atomicAdd(&g_done, 1u);
        s_last = (ticket == gridDim.x - 1) ? 1 : 0;
    }
    __syncthreads();

    // ---- fused finalize: only the last block to finish runs this ----
    if (s_last) {
        const int N = gridDim.x >> 2;   // boxes
        float fs = 0.0f;
        int   fc = 0;
        for (int b = t; b < N; b += 128) {
            float bsum = g_psum[4 * b] + g_psum[4 * b + 1] + g_psum[4 * b + 2] + g_psum[4 * b + 3];
            int   bcnt = g_pcnt[4 * b] + g_pcnt[4 * b + 1] + g_pcnt[4 * b + 2] + g_pcnt[4 * b + 3];
            if (bcnt >= 3) {
                fs += bsum / (float)max(bcnt, 1);
                fc += 1;
            }
        }
        ssum[t] = fs;
        scnt[t] = fc;
        __syncthreads();
#pragma unroll
        for (int off = 64; off > 0; off >>= 1) {
            if (t < off) {
                ssum[t] += ssum[t + off];
                scnt[t] += scnt[t + off];
            }
            __syncthreads();
        }
        if (t == 0) {
            out[0] = ssum[0] / (float)max(scnt[0], 1);
            g_done = 0;   // reset for next graph replay
        }
    }
}

extern "C" void kernel_launch(void* const* d_in, const int* in_sizes, int n_in,
                              void* d_out, int out_size) {
    const float*  wl      = (const float*)d_in[0];
    const float*  Ry      = (const float*)d_in[1];
    const float4* points4 = (const float4*)d_in[2];
    const float4* dens4   = (const float4*)d_in[3];
    const float*  center  = (const float*)d_in[4];
    float* out = (float*)d_out;

    const int N = in_sizes[1];        // Ry has N elements
    const int P = in_sizes[3] / N;    // density has N*P elements

    box_kernel<<<N * SPLIT, 128>>>(wl, Ry, points4, dens4, center, out, P);
}

// round 9
// speedup vs baseline: 1.1918x; 1.1918x over previous
#include <cuda_runtime.h>
#include <math_constants.h>

#define PI_F 3.14159265358979323846f

// Per-box intermediate results (N <= 8192 guard; actual N = 1024)
__device__ float        g_box_mean[8192];
__device__ int          g_box_valid[8192];
__device__ unsigned int g_done = 0;   // last-block ticket; reset by last block each call

__device__ __forceinline__ float frcp_approx(float x) {
    float r;
    asm("rcp.approx.f32 %0, %1;" : "=f"(r) : "f"(x));
    return r;
}

typedef unsigned long long u64;

__device__ __forceinline__ u64 pack2(float lo, float hi) {
    u64 r; asm("mov.b64 %0, {%1, %2};" : "=l"(r) : "f"(lo), "f"(hi)); return r;
}
__device__ __forceinline__ void unpack2(u64 v, float& lo, float& hi) {
    asm("mov.b64 {%0, %1}, %2;" : "=f"(lo), "=f"(hi) : "l"(v));
}
__device__ __forceinline__ u64 mul2(u64 a, u64 b) {
    u64 r; asm("mul.rn.f32x2 %0, %1, %2;" : "=l"(r) : "l"(a), "l"(b)); return r;
}
__device__ __forceinline__ u64 add2(u64 a, u64 b) {
    u64 r; asm("add.rn.f32x2 %0, %1, %2;" : "=l"(r) : "l"(a), "l"(b)); return r;
}
__device__ __forceinline__ u64 fma2(u64 a, u64 b, u64 c) {
    u64 r; asm("fma.rn.f32x2 %0, %1, %2, %3;" : "=l"(r) : "l"(a), "l"(b), "l"(c)); return r;
}

struct BoxConst {
    float k1, k2;
    u64 bs02, bs13;          // {bs0, bs2}, {bs1, bs3}
    u64 nmx02, nmx13;        // {-midx0, -midx2}, {-midx1, -midx3}
    u64 nmy02, nmy13;        // {-midy0, -midy2}, {-midy1, -midy3}
    float halfx[4], halfy[4];
};

// Process 4 points (q0,q1 hold xy pairs, d4 their densities) against the box.
__device__ __forceinline__ void process4(const BoxConst& C,
                                         float4 q0, float4 q1, float4 d4,
                                         float& lsum, int& lcnt) {
    const float PX[4] = {q0.x, q0.z, q1.x, q1.z};
    const float PY[4] = {q0.y, q0.w, q1.y, q1.w};
    const float DN[4] = {d4.x, d4.y, d4.z, d4.w};

#pragma unroll
    for (int h = 0; h < 4; h++) {
        const float px = (PX[h] == 0.0f) ? 0.0001f : PX[h];
        const float py = PY[h];
        const float slope = py * frcp_approx(px);
        const float s1 = 1.0f + fabsf(slope);     // dis = |ix-px| * s1

        const float rA = frcp_approx(slope - C.k1);   // edges 0, 2
        const float rB = frcp_approx(slope - C.k2);   // edges 1, 3

        const u64 sl2 = pack2(slope, slope);
        const u64 rA2 = pack2(rA, rA);
        const u64 rB2 = pack2(rB, rB);

        // packed: edges {0,2} and {1,3}
        const u64 ix02 = mul2(C.bs02, rA2);
        const u64 tx02 = add2(ix02, C.nmx02);
        const u64 ty02 = fma2(ix02, sl2, C.nmy02);   // iy - midy, iy fused away
        const u64 ix13 = mul2(C.bs13, rB2);
        const u64 tx13 = add2(ix13, C.nmx13);
        const u64 ty13 = fma2(ix13, sl2, C.nmy13);

        float ix[4], tx[4], ty[4];
        unpack2(ix02, ix[0], ix[2]);
        unpack2(tx02, tx[0], tx[2]);
        unpack2(ty02, ty[0], ty[2]);
        unpack2(ix13, ix[1], ix[3]);
        unpack2(tx13, tx[1], tx[3]);
        unpack2(ty13, ty[1], ty[3]);

        float best_aix = CUDART_INF_F;   // argmin key: |ix| (monotone with cen)
        float best_ix  = 0.0f;
        int   m = 0;

#pragma unroll
        for (int j = 0; j < 4; j++) {
            // float-space mask: equivalent to the rint(1e4*...) integer test
            // except on measure-zero half-integer ties
            const bool mask = (fabsf(tx[j]) < C.halfx[j]) |
                              (fabsf(ty[j]) < C.halfy[j]);
            m += mask ? 1 : 0;
            const bool better = mask & (fabsf(ix[j]) < best_aix);
            best_aix = better ? fabsf(ix[j]) : best_aix;
            best_ix  = better ? ix[j] : best_ix;
        }

        // branchless tail: weight is 0 unless exactly 2 masked edges
        const bool  m2  = (m == 2);
        const float dis = fabsf(best_ix - px) * s1;
        const float wgt = m2 ? frcp_approx(DN[h]) : 0.0f;
        lsum = fmaf(dis, wgt, lsum);
        lcnt += m2 ? 1 : 0;
    }
}

__global__ void __launch_bounds__(128, 7)
box_kernel(const float* __restrict__ wl,
           const float* __restrict__ Ry,
           const float4* __restrict__ points4,   // 2 points per float4
           const float4* __restrict__ density4,  // 4 densities per float4
           const float* __restrict__ center,
           float* __restrict__ out,
           int P) {
    const int n = blockIdx.x;
    const int t = threadIdx.x;

    // setup: [0]=k1 [1]=k2 [2..5]=bs [6..9]=midx [10..13]=halfx [14..17]=midy [18..21]=halfy
    __shared__ float s_set[22];
    __shared__ int   s_last;

    if (t == 0) {
        const float w  = wl[2 * n];
        const float l  = wl[2 * n + 1];
        const float ry = Ry[n];
        const float c0 = center[2 * n];
        const float c1 = center[2 * n + 1];

        const float init_theta = atanf(w / l);
        const float length     = sqrtf(w * w + l * l) * 0.5f;

        float angs[4];
        angs[0] = init_theta + ry;
        angs[1] = PI_F - init_theta + ry;
        angs[2] = PI_F + init_theta + ry;
        angs[3] = -init_theta + ry;

        float cx[4], cy[4];
#pragma unroll
        for (int j = 0; j < 4; j++) {
            cx[j] = length * cosf(angs[j]) + c0;
            cy[j] = length * sinf(angs[j]) + c1;
        }

        float ry2 = ry;
        if (ry2 == PI_F * 0.5f) ry2 -= 0.0001f;
        if (ry2 == 0.0f)        ry2 += 0.0001f;
        const float k1 = tanf(ry2);
        const float k2 = tanf(ry2 + PI_F * 0.5f);

        s_set[0] = k1;
        s_set[1] = k2;
        // bs order = {b11, b22, b12, b21}
        s_set[2] = cy[0] - k1 * cx[0];   // b11
        s_set[3] = cy[2] - k2 * cx[2];   // b22
        s_set[4] = cy[2] - k1 * cx[2];   // b12
        s_set[5] = cy[0] - k2 * cx[0];   // b21

        float cxr[4], cyr[4];
#pragma unroll
        for (int j = 0; j < 4; j++) {
            cxr[j] = rintf(cx[j] * 10000.0f);
            cyr[j] = rintf(cy[j] * 10000.0f);
        }
        const int nxt[4] = {1, 2, 3, 0};
#pragma unroll
        for (int j = 0; j < 4; j++) {
            const int jn = nxt[j];
            const float lox = fminf(cxr[j], cxr[jn]);
            const float hix = fmaxf(cxr[j], cxr[jn]);
            const float loy = fminf(cyr[j], cyr[jn]);
            const float hiy = fmaxf(cyr[j], cyr[jn]);
            // shrink by 0.5 (rint threshold), rescale to float space
            const float loxp = (lox + 0.5f) * 1e-4f;
            const float hixp = (hix - 0.5f) * 1e-4f;
            const float loyp = (loy + 0.5f) * 1e-4f;
            const float hiyp = (hiy - 0.5f) * 1e-4f;
            s_set[6  + j] = 0.5f * (loxp + hixp);   // midx
            s_set[10 + j] = 0.5f * (hixp - loxp);   // halfx (<=0 => always-false, matches ref)
            s_set[14 + j] = 0.5f * (loyp + hiyp);   // midy
            s_set[18 + j] = 0.5f * (hiyp - loyp);   // halfy
        }
    }
    __syncthreads();

    BoxConst C;
    C.k1 = s_set[0];
    C.k2 = s_set[1];
    C.bs02  = pack2(s_set[2], s_set[4]);
    C.bs13  = pack2(s_set[3], s_set[5]);
    C.nmx02 = pack2(-s_set[6], -s_set[8]);
    C.nmx13 = pack2(-s_set[7], -s_set[9]);
    C.nmy02 = pack2(-s_set[14], -s_set[16]);
    C.nmy13 = pack2(-s_set[15], -s_set[17]);
#pragma unroll
    for (int j = 0; j < 4; j++) {
        C.halfx[j] = s_set[10 + j];
        C.halfy[j] = s_set[18 + j];
    }

    const float4* pts4 = points4  + (size_t)n * (P / 2);
    const float4* dns4 = density4 + (size_t)n * (P / 4);

    float lsum = 0.0f;
    int   lcnt = 0;

    // 8 points per iteration: two 4-point units (i and i + P/8), loads front-batched.
    const int eighth = P / 8;
    for (int i = t; i < eighth; i += 128) {
        const int i2 = i + eighth;
        const float4 a0 = pts4[2 * i];
        const float4 a1 = pts4[2 * i + 1];
        const float4 b0 = pts4[2 * i2];
        const float4 b1 = pts4[2 * i2 + 1];
        const float4 da = dns4[i];
        const float4 db = dns4[i2];

        process4(C, a0, a1, da, lsum, lcnt);
        process4(C, b0, b1, db, lsum, lcnt);
    }

    // ---- block reduction (128 threads) ----
    __shared__ float ssum[128];
    __shared__ int   scnt[128];
    ssum[t] = lsum;
    scnt[t] = lcnt;
    __syncthreads();
#pragma unroll
    for (int off = 64; off > 0; off >>= 1) {
        if (t < off) {
            ssum[t] += ssum[t + off];
            scnt[t] += scnt[t + off];
        }
        __syncthreads();
    }

    if (t == 0) {
        const int cnt = scnt[0];
        g_box_valid[n] = (cnt >= 3) ? 1 : 0;
        g_box_mean[n]  = ssum[0] / (float)max(cnt, 1);
        __threadfence();
        const unsigned int ticket = atomicAdd(&g_done, 1u);
        s_last = (ticket == gridDim.x - 1) ? 1 : 0;
    }
    __syncthreads();

    // ---- fused finalize: only the last block to finish runs this ----
    if (s_last) {
        const int N = gridDim.x;
        float s = 0.0f;
        int   c = 0;
        for (int i = t; i < N; i += 128) {
            if (g_box_valid[i]) {
                s += g_box_mean[i];
                c += 1;
            }
        }
        ssum[t] = s;
        scnt[t] = c;
        __syncthreads();
#pragma unroll
        for (int off = 64; off > 0; off >>= 1) {
            if (t < off) {
                ssum[t] += ssum[t + off];
                scnt[t] += scnt[t + off];
            }
            __syncthreads();
        }
        if (t == 0) {
            out[0] = ssum[0] / (float)max(scnt[0], 1);
            g_done = 0;   // reset for next graph replay
        }
    }
}

extern "C" void kernel_launch(void* const* d_in, const int* in_sizes, int n_in,
                              void* d_out, int out_size) {
    const float*  wl      = (const float*)d_in[0];
    const float*  Ry      = (const float*)d_in[1];
    const float4* points4 = (const float4*)d_in[2];
    const float4* dens4   = (const float4*)d_in[3];
    const float*  center  = (const float*)d_in[4];
    float* out = (float*)d_out;

    const int N = in_sizes[1];        // Ry has N elements
    const int P = in_sizes[3] / N;    // density has N*P elements

    box_kernel<<<N, 128>>>(wl, Ry, points4, dens4, center, out, P);
}

// round 14
// speedup vs baseline: 1.4581x; 1.2235x over previous
#include <cuda_runtime.h>
#include <math_constants.h>

#define PI_F 3.14159265358979323846f

// Per-box intermediate results (N <= 8192 guard; actual N = 1024)
__device__ float        g_box_mean[8192];
__device__ int          g_box_valid[8192];
__device__ unsigned int g_done = 0;   // last-block ticket; reset by last block each call

__device__ __forceinline__ float frcp_approx(float x) {
    float r;
    asm("rcp.approx.f32 %0, %1;" : "=f"(r) : "f"(x));
    return r;
}

struct BoxConst {
    float k1, k2;
    float bsA0, bsA1;   // pair A (slope k1): b11, b12
    float bsB0, bsB1;   // pair B (slope k2): b22, b21
};

// Process 4 points (q0,q1 hold xy pairs, d4 their densities) against the box.
// Slab method: box = slabA ∩ slabB; along ray y=slope*x the slab-A occupancy is
// exactly x in [min(ixA0,ixA1), max(...)], same for B. Crossing <=> xin < xout,
// and the two boundary hits are the reference's two masked edges; closest-to-origin
// (min |ix|, == argmin cen) selects the reported intersection.
__device__ __forceinline__ void process4(const BoxConst& C,
                                         float4 q0, float4 q1, float4 d4,
                                         float& lsum, int& lcnt) {
    const float PX[4] = {q0.x, q0.z, q1.x, q1.z};
    const float PY[4] = {q0.y, q0.w, q1.y, q1.w};
    const float DN[4] = {d4.x, d4.y, d4.z, d4.w};

#pragma unroll
    for (int h = 0; h < 4; h++) {
        const float px = (PX[h] == 0.0f) ? 0.0001f : PX[h];
        const float py = PY[h];
        const float slope = py * frcp_approx(px);
        const float s1 = 1.0f + fabsf(slope);        // dis = |ix-px| * (1+|slope|)

        const float rA = frcp_approx(slope - C.k1);
        const float rB = frcp_approx(slope - C.k2);

        const float ixA0 = C.bsA0 * rA;
        const float ixA1 = C.bsA1 * rA;
        const float ixB0 = C.bsB0 * rB;
        const float ixB1 = C.bsB1 * rB;

        const float loA = fminf(ixA0, ixA1);
        const float hiA = fmaxf(ixA0, ixA1);
        const float loB = fminf(ixB0, ixB1);
        const float hiB = fmaxf(ixB0, ixB1);

        const float xin  = fmaxf(loA, loB);
        const float xout = fminf(hiA, hiB);

        const bool  cross = xin < xout;
        const float best  = (fabsf(xin) < fabsf(xout)) ? xin : xout;
        const float dis   = fabsf(best - px) * s1;
        const float wgt   = cross ? frcp_approx(DN[h]) : 0.0f;
        lsum  = fmaf(dis, wgt, lsum);
        lcnt += cross ? 1 : 0;
    }
}

__global__ void __launch_bounds__(128, 8)
box_kernel(const float* __restrict__ wl,
           const float* __restrict__ Ry,
           const float4* __restrict__ points4,   // 2 points per float4
           const float4* __restrict__ density4,  // 4 densities per float4
           const float* __restrict__ center,
           float* __restrict__ out,
           int P) {
    const int n = blockIdx.x;
    const int t = threadIdx.x;

    // setup: [0]=k1 [1]=k2 [2]=b11 [3]=b12 [4]=b22 [5]=b21
    __shared__ float s_set[6];
    __shared__ int   s_last;

    if (t == 0) {
        const float w  = wl[2 * n];
        const float l  = wl[2 * n + 1];
        const float ry = Ry[n];
        const float c0 = center[2 * n];
        const float c1 = center[2 * n + 1];

        const float init_theta = atanf(w / l);
        const float length     = sqrtf(w * w + l * l) * 0.5f;

        // corners 0 and 2 are all that's needed for the b offsets
        const float a0 = init_theta + ry;
        const float a2 = PI_F + init_theta + ry;
        const float cx0 = length * cosf(a0) + c0;
        const float cy0 = length * sinf(a0) + c1;
        const float cx2 = length * cosf(a2) + c0;
        const float cy2 = length * sinf(a2) + c1;

        float ry2 = ry;
        if (ry2 == PI_F * 0.5f) ry2 -= 0.0001f;
        if (ry2 == 0.0f)        ry2 += 0.0001f;
        const float k1 = tanf(ry2);
        const float k2 = tanf(ry2 + PI_F * 0.5f);

        s_set[0] = k1;
        s_set[1] = k2;
        s_set[2] = cy0 - k1 * cx0;   // b11
        s_set[3] = cy2 - k1 * cx2;   // b12
        s_set[4] = cy2 - k2 * cx2;   // b22
        s_set[5] = cy0 - k2 * cx0;   // b21
    }
    __syncthreads();

    BoxConst C;
    C.k1   = s_set[0];
    C.k2   = s_set[1];
    C.bsA0 = s_set[2];
    C.bsA1 = s_set[3];
    C.bsB0 = s_set[4];
    C.bsB1 = s_set[5];

    const float4* pts4 = points4  + (size_t)n * (P / 2);
    const float4* dns4 = density4 + (size_t)n * (P / 4);

    float lsum = 0.0f;
    int   lcnt = 0;

    // 8 points per iteration: two 4-point units (i and i + P/8), loads front-batched.
    const int eighth = P / 8;
    for (int i = t; i < eighth; i += 128) {
        const int i2 = i + eighth;
        const float4 a0 = pts4[2 * i];
        const float4 a1 = pts4[2 * i + 1];
        const float4 b0 = pts4[2 * i2];
        const float4 b1 = pts4[2 * i2 + 1];
        const float4 da = dns4[i];
        const float4 db = dns4[i2];

        process4(C, a0, a1, da, lsum, lcnt);
        process4(C, b0, b1, db, lsum, lcnt);
    }

    // ---- block reduction (128 threads) ----
    __shared__ float ssum[128];
    __shared__ int   scnt[128];
    ssum[t] = lsum;
    scnt[t] = lcnt;
    __syncthreads();
#pragma unroll
    for (int off = 64; off > 0; off >>= 1) {
        if (t < off) {
            ssum[t] += ssum[t + off];
            scnt[t] += scnt[t + off];
        }
        __syncthreads();
    }

    if (t == 0) {
        const int cnt = scnt[0];
        g_box_valid[n] = (cnt >= 3) ? 1 : 0;
        g_box_mean[n]  = ssum[0] / (float)max(cnt, 1);
        __threadfence();
        const unsigned int ticket = atomicAdd(&g_done, 1u);
        s_last = (ticket == gridDim.x - 1) ? 1 : 0;
    }
    __syncthreads();

    // ---- fused finalize: only the last block to finish runs this ----
    if (s_last) {
        const int N = gridDim.x;
        float s = 0.0f;
        int   c = 0;
        for (int i = t; i < N; i += 128) {
            if (g_box_valid[i]) {
                s += g_box_mean[i];
                c += 1;
            }
        }
        ssum[t] = s;
        scnt[t] = c;
        __syncthreads();
#pragma unroll
        for (int off = 64; off > 0; off >>= 1) {
            if (t < off) {
                ssum[t] += ssum[t + off];
                scnt[t] += scnt[t + off];
            }
            __syncthreads();
        }
        if (t == 0) {
            out[0] = ssum[0] / (float)max(scnt[0], 1);
            g_done = 0;   // reset for next graph replay
        }
    }
}

extern "C" void kernel_launch(void* const* d_in, const int* in_sizes, int n_in,
                              void* d_out, int out_size) {
    const float*  wl      = (const float*)d_in[0];
    const float*  Ry      = (const float*)d_in[1];
    const float4* points4 = (const float4*)d_in[2];
    const float4* dens4   = (const float4*)d_in[3];
    const float*  center  = (const float*)d_in[4];
    float* out = (float*)d_out;

    const int N = in_sizes[1];        // Ry has N elements
    const int P = in_sizes[3] / N;    // density has N*P elements

    box_kernel<<<N, 128>>>(wl, Ry, points4, dens4, center, out, P);
}